// round 4
// baseline (speedup 1.0000x reference)
#include <cuda_runtime.h>
#include <cuda_bf16.h>
#include <cstdint>

// ============================================================================
// Split-bf16 mma.sync implicit-GEMM conv, round 4.
// Pre-pass kernels materialize A(w) and B(im2col x) as {hi,lo} bf16 planes in
// the EXACT swizzled smem-tile layout. Mainloop copies tiles with cp.async
// (3-stage pipeline) and runs pure HMMA. 3 MMAs per k16: ah*bh + ah*bl + al*bh.
// ============================================================================

#define KTOT   2304
#define KCH    72            // 2304 / 32
#define NPIMG  2916
#define OUTIMG (512*NPIMG)
#define XIMG   (256*3136)

#define TILE_BYTES 16384     // one operand tile: [hi 8KB][lo 8KB]
#define STAGE_BYTES 32768    // A tile + B tile
#define NSTAGE 3
#define SMEM_BYTES (NSTAGE*STAGE_BYTES)   // 98304

// Pre-transformed operands in smem layout:
//   A: [mt(4)][ch(72)][hi 8KB][lo 8KB]   row m: 64B, elem k at (2k)^swz(m)
//   B: [nt(729)][ch(72)][hi 8KB][lo 8KB] row n: 64B, swz(n) = ((n>>1)&3)<<4
__device__ __align__(16) unsigned char g_asplit[4ull*72*16384];           // 4.7MB
__device__ __align__(16) unsigned char g_bsplit[729ull*72*16384];         // 860MB

// ---------------------------------------------------------------------------
__device__ __forceinline__ uint32_t smem_u32(const void* p) {
    uint32_t a;
    asm("{ .reg .u64 t; cvta.to.shared.u64 t, %1; cvt.u32.u64 %0, t; }"
        : "=r"(a) : "l"(p));
    return a;
}
__device__ __forceinline__ void ldsm4(uint32_t a, uint32_t& r0, uint32_t& r1,
                                      uint32_t& r2, uint32_t& r3) {
    asm volatile("ldmatrix.sync.aligned.m8n8.x4.shared.b16 {%0,%1,%2,%3}, [%4];"
                 : "=r"(r0), "=r"(r1), "=r"(r2), "=r"(r3) : "r"(a));
}
__device__ __forceinline__ void mma_bf16(float* c, const uint32_t* a,
                                         uint32_t b0, uint32_t b1) {
    asm volatile(
        "mma.sync.aligned.m16n8k16.row.col.f32.bf16.bf16.f32 "
        "{%0,%1,%2,%3}, {%4,%5,%6,%7}, {%8,%9}, {%0,%1,%2,%3};"
        : "+f"(c[0]), "+f"(c[1]), "+f"(c[2]), "+f"(c[3])
        : "r"(a[0]), "r"(a[1]), "r"(a[2]), "r"(a[3]), "r"(b0), "r"(b1));
}
__device__ __forceinline__ void cpasync16(uint32_t dst, const void* src) {
    asm volatile("cp.async.cg.shared.global [%0], [%1], 16;"
                 :: "r"(dst), "l"(src) : "memory");
}
__device__ __forceinline__ void cp_commit() {
    asm volatile("cp.async.commit_group;" ::: "memory");
}
__device__ __forceinline__ void cp_wait2() {
    asm volatile("cp.async.wait_group 2;" ::: "memory");
}

// fp32 -> {hi,lo} bf16 split, two values packed per u32 plane word
__device__ __forceinline__ void split2(float a, float b, uint32_t& h, uint32_t& l) {
    __nv_bfloat16 ha = __float2bfloat16_rn(a);
    __nv_bfloat16 hb = __float2bfloat16_rn(b);
    __nv_bfloat16 la = __float2bfloat16_rn(a - __bfloat162float(ha));
    __nv_bfloat16 lb = __float2bfloat16_rn(b - __bfloat162float(hb));
    h = (uint32_t)*(uint16_t*)&ha | ((uint32_t)*(uint16_t*)&hb << 16);
    l = (uint32_t)*(uint16_t*)&la | ((uint32_t)*(uint16_t*)&lb << 16);
}
__device__ __forceinline__ int koff(int k) {
    int ci = k / 9, r9 = k - ci * 9;
    int kh = r9 / 3, kw = r9 - kh * 3;
    return ci * 3136 + kh * 56 + kw;
}

// ---------------------------------------------------------------------------
// prep kernels
// ---------------------------------------------------------------------------
__global__ void prep_a(const float* __restrict__ w) {
    int i = blockIdx.x * 256 + threadIdx.x;        // 147456 total
    int co = i / 288;
    int r  = i - co * 288;
    int ch = r >> 2, kq = r & 3;
    const float4* p = (const float4*)(w + (size_t)co * KTOT + ch * 32 + kq * 8);
    float4 v0 = p[0], v1 = p[1];
    uint32_t h[4], l[4];
    split2(v0.x, v0.y, h[0], l[0]);
    split2(v0.z, v0.w, h[1], l[1]);
    split2(v1.x, v1.y, h[2], l[2]);
    split2(v1.z, v1.w, h[3], l[3]);
    int m = co & 127;
    size_t base = ((size_t)(co >> 7) * KCH + ch) * TILE_BYTES
                + m * 64 + (((uint32_t)kq * 16) ^ ((((uint32_t)m >> 1) & 3) << 4));
    *(uint4*)(g_asplit + base)        = make_uint4(h[0], h[1], h[2], h[3]);
    *(uint4*)(g_asplit + base + 8192) = make_uint4(l[0], l[1], l[2], l[3]);
}

__global__ void prep_b(const float* __restrict__ x) {
    int i = blockIdx.x * 256 + threadIdx.x;        // 26873856 total
    int nt = i / 36864;
    int r  = i - nt * 36864;
    int ch = r >> 9;
    int r2 = r & 511;
    int n  = r2 >> 2, kq = r2 & 3;
    int ng = nt * 128 + n;
    int bimg = ng / NPIMG;
    int prem = ng - bimg * NPIMG;
    int oh = prem / 54, ow = prem - oh * 54;
    const float* xb = x + (size_t)bimg * XIMG + oh * 56 + ow;
    int kbase = ch * 32 + kq * 8;
    uint32_t h[4], l[4];
    #pragma unroll
    for (int j = 0; j < 4; ++j) {
        float a = xb[koff(kbase + 2*j)];
        float b = xb[koff(kbase + 2*j + 1)];
        split2(a, b, h[j], l[j]);
    }
    size_t base = ((size_t)nt * KCH + ch) * TILE_BYTES
                + n * 64 + (((uint32_t)kq * 16) ^ ((((uint32_t)n >> 1) & 3) << 4));
    *(uint4*)(g_bsplit + base)        = make_uint4(h[0], h[1], h[2], h[3]);
    *(uint4*)(g_bsplit + base + 8192) = make_uint4(l[0], l[1], l[2], l[3]);
}

// ---------------------------------------------------------------------------
// mainloop MMA on one 32-k chunk (layout identical to round 3)
// buf: [Ahi 0][Alo 8K][Bhi 16K][Blo 24K]
// ---------------------------------------------------------------------------
__device__ __forceinline__ void mma_chunk(
    uint32_t bufb, float (&acc)[4][4][4],
    uint32_t aRowOff, uint32_t aKext, uint32_t aSwz,
    uint32_t bRowOff, uint32_t bKext, uint32_t bSwz)
{
    #pragma unroll
    for (int kb = 0; kb < 2; ++kb) {
        const uint32_t kb2 = (uint32_t)kb * 32;
        const uint32_t aK = (kb2 + aKext) ^ aSwz;
        const uint32_t bK = (kb2 + bKext) ^ bSwz;

        uint32_t bh[8], bl[8];
        const uint32_t bAddr = bufb + 16384 + bRowOff + bK;
        ldsm4(bAddr,               bh[0], bh[1], bh[2], bh[3]);
        ldsm4(bAddr + 1024,        bh[4], bh[5], bh[6], bh[7]);
        ldsm4(bAddr + 8192,        bl[0], bl[1], bl[2], bl[3]);
        ldsm4(bAddr + 8192 + 1024, bl[4], bl[5], bl[6], bl[7]);

        uint32_t a[16];
        const uint32_t aAddr = bufb + aRowOff + aK;
        #pragma unroll
        for (int am = 0; am < 4; ++am)
            ldsm4(aAddr + am * 1024, a[4*am], a[4*am+1], a[4*am+2], a[4*am+3]);

        #pragma unroll
        for (int am = 0; am < 4; ++am)
            #pragma unroll
            for (int an = 0; an < 4; ++an) {
                mma_bf16(acc[am][an], a + 4*am, bh[2*an], bh[2*an+1]);
                mma_bf16(acc[am][an], a + 4*am, bl[2*an], bl[2*an+1]);
            }

        #pragma unroll
        for (int am = 0; am < 4; ++am)
            ldsm4(aAddr + 8192 + am * 1024, a[4*am], a[4*am+1], a[4*am+2], a[4*am+3]);

        #pragma unroll
        for (int am = 0; am < 4; ++am)
            #pragma unroll
            for (int an = 0; an < 4; ++an)
                mma_bf16(acc[am][an], a + 4*am, bh[2*an], bh[2*an+1]);
    }
}

// ---------------------------------------------------------------------------
__global__ void __launch_bounds__(256, 2)
conv_mma_kernel(float* __restrict__ out)
{
    extern __shared__ char smem[];
    const uint32_t sb = smem_u32(smem);
    const int tid = threadIdx.x;
    const int bm = blockIdx.x;        // 0..3   (x fastest -> 4 bm CTAs share B tile in L2)
    const int bn = blockIdx.y;        // 0..728

    const unsigned char* aBase = g_asplit + (size_t)bm * KCH * TILE_BYTES;
    const unsigned char* bBase = g_bsplit + (size_t)bn * KCH * TILE_BYTES;

    // per-thread copy source/dst offsets
    const bool isA = (tid < 128);
    const int  ct  = isA ? tid : (tid - 128);
    const uint32_t dOff = (isA ? 0u : 16384u) + (uint32_t)ct * 128;
    const unsigned char* sBase = (isA ? aBase : bBase) + ct * 128;

    // mma invariants: warp grid 2(m) x 4(n)
    const int lane = tid & 31, wid = tid >> 5;
    const int wm = wid & 1, wn = wid >> 1;
    const uint32_t aRowOff = (uint32_t)(wm * 64 + (lane & 15)) * 64;
    const uint32_t aKext   = (uint32_t)(lane >> 4) << 4;
    const uint32_t aSwz    = (uint32_t)(((lane & 15) >> 1) & 3) << 4;
    const uint32_t bRowOff = (uint32_t)(wn * 32 + (lane & 7) + ((lane >> 4) << 3)) * 64;
    const uint32_t bKext   = (uint32_t)((lane >> 3) & 1) << 4;
    const uint32_t bSwz    = (uint32_t)(((lane & 7) >> 1) & 3) << 4;

    float acc[4][4][4];
    #pragma unroll
    for (int i = 0; i < 4; ++i)
        #pragma unroll
        for (int j = 0; j < 4; ++j)
            #pragma unroll
            for (int r = 0; r < 4; ++r) acc[i][j][r] = 0.0f;

    // prologue: fill 3 stages
    #pragma unroll
    for (int s = 0; s < NSTAGE; ++s) {
        const unsigned char* src = sBase + (size_t)s * TILE_BYTES;
        const uint32_t dst = sb + s * STAGE_BYTES + dOff;
        #pragma unroll
        for (int j = 0; j < 8; ++j) cpasync16(dst + j * 16, src + j * 16);
        cp_commit();
    }

    int stage = 0;
    for (int ch = 0; ch < KCH; ++ch) {
        cp_wait2();
        __syncthreads();
        mma_chunk(sb + stage * STAGE_BYTES, acc,
                  aRowOff, aKext, aSwz, bRowOff, bKext, bSwz);
        __syncthreads();
        if (ch + NSTAGE < KCH) {
            const unsigned char* src = sBase + (size_t)(ch + NSTAGE) * TILE_BYTES;
            const uint32_t dst = sb + stage * STAGE_BYTES + dOff;
            #pragma unroll
            for (int j = 0; j < 8; ++j) cpasync16(dst + j * 16, src + j * 16);
        }
        cp_commit();
        stage = (stage + 1 == NSTAGE) ? 0 : stage + 1;
    }

    // epilogue: acc[am][an] rows co, co+8 ; cols gn, gn+1 (float2, same image)
    const int lane4 = lane >> 2, lane2 = (lane & 3) * 2;
    #pragma unroll
    for (int an = 0; an < 4; ++an) {
        const int gn = bn * 128 + wn * 32 + an * 8 + lane2;
        const int b2 = gn / NPIMG;
        const int r2 = gn - b2 * NPIMG;
        float* op = out + (size_t)b2 * OUTIMG + r2;
        #pragma unroll
        for (int am = 0; am < 4; ++am) {
            const int co = bm * 128 + wm * 64 + am * 16 + lane4;
            *(float2*)(op + (size_t)co * NPIMG) =
                make_float2(acc[am][an][0], acc[am][an][1]);
            *(float2*)(op + (size_t)(co + 8) * NPIMG) =
                make_float2(acc[am][an][2], acc[am][an][3]);
        }
    }
}

// ---------------------------------------------------------------------------
extern "C" void kernel_launch(void* const* d_in, const int* in_sizes, int n_in,
                              void* d_out, int out_size)
{
    const float* x = (const float*)d_in[0];   // [32,256,56,56]
    const float* w = (const float*)d_in[1];   // [512,256,3,3]
    float* out = (float*)d_out;               // [32,512,54,54]

    cudaFuncSetAttribute(conv_mma_kernel,
                         cudaFuncAttributeMaxDynamicSharedMemorySize, SMEM_BYTES);

    prep_a<<<576, 256>>>(w);                  // 147456 threads
    prep_b<<<104976, 256>>>(x);               // 26873856 threads
    conv_mma_kernel<<<dim3(4, 729), 256, SMEM_BYTES>>>(out);
}

// round 5
// speedup vs baseline: 1.3918x; 1.3918x over previous
#include <cuda_runtime.h>
#include <cuda_bf16.h>
#include <cstdint>

// ============================================================================
// Split-bf16 mma.sync implicit-GEMM conv, round 5.
// A (weights): pre-split/swizzled by prep_a (4.7MB, L2-resident), copied into
//   smem with cp.async.cg (validated in round 4).
// B (im2col x): inline gather from packed {hi,lo} x (validated in round 3).
// Grid (bm fastest): 4 co-resident CTAs share identical x gathers in L2.
// 3 MMAs per k16: ah*bh + ah*bl + al*bh. fp32 accum in registers.
// ============================================================================

#define KTOT   2304
#define KCH    72            // 2304 / 32
#define NPIMG  2916
#define OUTIMG (512*NPIMG)
#define XIMG   (256*3136)

#define TILE_BYTES  16384    // [hi 8KB][lo 8KB]
#define STAGE_BYTES 32768    // A tile + B tile
#define OFF_B       16384
#define OFF_KOFF    65536                  // after 2 stages
#define SMEM_BYTES  (OFF_KOFF + KTOT*4)    // 74752

// A pre-split into exact swizzled smem-tile layout: [mt(4)][ch(72)][hi|lo]
__device__ __align__(16) unsigned char g_asplit[4ull*72*16384];          // 4.7MB
// x packed {hi,lo} bf16x2 per element
__device__ __nv_bfloat162 g_xpack[32 * 256 * 56 * 56];                   // 103MB

// ---------------------------------------------------------------------------
__device__ __forceinline__ uint32_t smem_u32(const void* p) {
    uint32_t a;
    asm("{ .reg .u64 t; cvta.to.shared.u64 t, %1; cvt.u32.u64 %0, t; }"
        : "=r"(a) : "l"(p));
    return a;
}
__device__ __forceinline__ void sts64(uint32_t addr, uint32_t a, uint32_t b) {
    asm volatile("st.shared.v2.b32 [%0], {%1, %2};" :: "r"(addr), "r"(a), "r"(b));
}
__device__ __forceinline__ void ldsm4(uint32_t a, uint32_t& r0, uint32_t& r1,
                                      uint32_t& r2, uint32_t& r3) {
    asm volatile("ldmatrix.sync.aligned.m8n8.x4.shared.b16 {%0,%1,%2,%3}, [%4];"
                 : "=r"(r0), "=r"(r1), "=r"(r2), "=r"(r3) : "r"(a));
}
__device__ __forceinline__ void mma_bf16(float* c, const uint32_t* a,
                                         uint32_t b0, uint32_t b1) {
    asm volatile(
        "mma.sync.aligned.m16n8k16.row.col.f32.bf16.bf16.f32 "
        "{%0,%1,%2,%3}, {%4,%5,%6,%7}, {%8,%9}, {%0,%1,%2,%3};"
        : "+f"(c[0]), "+f"(c[1]), "+f"(c[2]), "+f"(c[3])
        : "r"(a[0]), "r"(a[1]), "r"(a[2]), "r"(a[3]), "r"(b0), "r"(b1));
}
__device__ __forceinline__ void cpasync16(uint32_t dst, const void* src) {
    asm volatile("cp.async.cg.shared.global [%0], [%1], 16;"
                 :: "r"(dst), "l"(src) : "memory");
}
__device__ __forceinline__ void cp_commit() {
    asm volatile("cp.async.commit_group;" ::: "memory");
}
__device__ __forceinline__ void cp_wait0() {
    asm volatile("cp.async.wait_group 0;" ::: "memory");
}

__device__ __forceinline__ void split2(float a, float b, uint32_t& h, uint32_t& l) {
    __nv_bfloat16 ha = __float2bfloat16_rn(a);
    __nv_bfloat16 hb = __float2bfloat16_rn(b);
    __nv_bfloat16 la = __float2bfloat16_rn(a - __bfloat162float(ha));
    __nv_bfloat16 lb = __float2bfloat16_rn(b - __bfloat162float(hb));
    h = (uint32_t)*(uint16_t*)&ha | ((uint32_t)*(uint16_t*)&hb << 16);
    l = (uint32_t)*(uint16_t*)&la | ((uint32_t)*(uint16_t*)&lb << 16);
}
__device__ __forceinline__ uint32_t pack_hl(float v) {
    __nv_bfloat16 hi = __float2bfloat16_rn(v);
    float r = v - __bfloat162float(hi);
    __nv_bfloat16 lo = __float2bfloat16_rn(r);
    __nv_bfloat162 p; p.x = hi; p.y = lo;
    return *reinterpret_cast<uint32_t*>(&p);
}

// ---------------------------------------------------------------------------
// prep kernels (both validated in earlier rounds)
// ---------------------------------------------------------------------------
__global__ void pack_x_kernel(const float* __restrict__ x) {
    int i = blockIdx.x * blockDim.x + threadIdx.x;   // 6422528 total
    float4 v = ((const float4*)x)[i];
    ((uint4*)g_xpack)[i] = make_uint4(pack_hl(v.x), pack_hl(v.y),
                                      pack_hl(v.z), pack_hl(v.w));
}
__global__ void prep_a(const float* __restrict__ w) {
    int i = blockIdx.x * 256 + threadIdx.x;          // 147456 total
    int co = i / 288;
    int r  = i - co * 288;
    int ch = r >> 2, kq = r & 3;
    const float4* p = (const float4*)(w + (size_t)co * KTOT + ch * 32 + kq * 8);
    float4 v0 = p[0], v1 = p[1];
    uint32_t h[4], l[4];
    split2(v0.x, v0.y, h[0], l[0]);
    split2(v0.z, v0.w, h[1], l[1]);
    split2(v1.x, v1.y, h[2], l[2]);
    split2(v1.z, v1.w, h[3], l[3]);
    int m = co & 127;
    size_t base = ((size_t)(co >> 7) * KCH + ch) * TILE_BYTES
                + m * 64 + (((uint32_t)kq * 16) ^ ((((uint32_t)m >> 1) & 3) << 4));
    *(uint4*)(g_asplit + base)        = make_uint4(h[0], h[1], h[2], h[3]);
    *(uint4*)(g_asplit + base + 8192) = make_uint4(l[0], l[1], l[2], l[3]);
}

// ---------------------------------------------------------------------------
// B producer (round-3 code): one 32-k chunk of im2col x into buffer bufb.
// thread -> (row n = tid>>1, khalf = tid&1); 16 LDG.32 + PRMT split + STS.64
// ---------------------------------------------------------------------------
__device__ __forceinline__ void produce_b(
    int ch, uint32_t bufb, const __nv_bfloat162* xb,
    uint32_t koffs, int prow, int khalf, uint32_t pswz)
{
    uint32_t bx[16];
    const uint32_t kb4 = koffs + (uint32_t)(ch * 32 + khalf * 16) * 4;
    #pragma unroll
    for (int g = 0; g < 4; ++g) {
        uint32_t k0, k1, k2, k3;
        asm volatile("ld.shared.v4.b32 {%0,%1,%2,%3}, [%4];"
                     : "=r"(k0), "=r"(k1), "=r"(k2), "=r"(k3)
                     : "r"(kb4 + g * 16));
        bx[4*g+0] = *(const uint32_t*)(xb + k0);
        bx[4*g+1] = *(const uint32_t*)(xb + k1);
        bx[4*g+2] = *(const uint32_t*)(xb + k2);
        bx[4*g+3] = *(const uint32_t*)(xb + k3);
    }
    const uint32_t sB = bufb + OFF_B + (uint32_t)prow * 64;
    const uint32_t kobase = (uint32_t)khalf * 32;
    #pragma unroll
    for (int g = 0; g < 4; ++g) {
        uint32_t h0 = __byte_perm(bx[4*g+0], bx[4*g+1], 0x5410);
        uint32_t h1 = __byte_perm(bx[4*g+2], bx[4*g+3], 0x5410);
        uint32_t l0 = __byte_perm(bx[4*g+0], bx[4*g+1], 0x7632);
        uint32_t l1 = __byte_perm(bx[4*g+2], bx[4*g+3], 0x7632);
        uint32_t ko = (kobase + 8u * g) ^ pswz;
        sts64(sB + ko, h0, h1);
        sts64(sB + 8192 + ko, l0, l1);
    }
}

// ---------------------------------------------------------------------------
// MMA consumer on one 32-k chunk (identical to rounds 3/4)
// buf: [Ahi 0][Alo 8K][Bhi 16K][Blo 24K]
// ---------------------------------------------------------------------------
__device__ __forceinline__ void mma_chunk(
    uint32_t bufb, float (&acc)[4][4][4],
    uint32_t aRowOff, uint32_t aKext, uint32_t aSwz,
    uint32_t bRowOff, uint32_t bKext, uint32_t bSwz)
{
    #pragma unroll
    for (int kb = 0; kb < 2; ++kb) {
        const uint32_t kb2 = (uint32_t)kb * 32;
        const uint32_t aK = (kb2 + aKext) ^ aSwz;
        const uint32_t bK = (kb2 + bKext) ^ bSwz;

        uint32_t bh[8], bl[8];
        const uint32_t bAddr = bufb + OFF_B + bRowOff + bK;
        ldsm4(bAddr,               bh[0], bh[1], bh[2], bh[3]);
        ldsm4(bAddr + 1024,        bh[4], bh[5], bh[6], bh[7]);
        ldsm4(bAddr + 8192,        bl[0], bl[1], bl[2], bl[3]);
        ldsm4(bAddr + 8192 + 1024, bl[4], bl[5], bl[6], bl[7]);

        uint32_t a[16];
        const uint32_t aAddr = bufb + aRowOff + aK;
        #pragma unroll
        for (int am = 0; am < 4; ++am)
            ldsm4(aAddr + am * 1024, a[4*am], a[4*am+1], a[4*am+2], a[4*am+3]);

        #pragma unroll
        for (int am = 0; am < 4; ++am)
            #pragma unroll
            for (int an = 0; an < 4; ++an) {
                mma_bf16(acc[am][an], a + 4*am, bh[2*an], bh[2*an+1]);
                mma_bf16(acc[am][an], a + 4*am, bl[2*an], bl[2*an+1]);
            }

        #pragma unroll
        for (int am = 0; am < 4; ++am)
            ldsm4(aAddr + 8192 + am * 1024, a[4*am], a[4*am+1], a[4*am+2], a[4*am+3]);

        #pragma unroll
        for (int am = 0; am < 4; ++am)
            #pragma unroll
            for (int an = 0; an < 4; ++an)
                mma_bf16(acc[am][an], a + 4*am, bh[2*an], bh[2*an+1]);
    }
}

// ---------------------------------------------------------------------------
__global__ void __launch_bounds__(256, 2)
conv_mma_kernel(float* __restrict__ out)
{
    extern __shared__ char smem[];
    const uint32_t sb = smem_u32(smem);
    const int tid = threadIdx.x;
    const int bm = blockIdx.x;        // 0..3, fastest -> x gathers shared in L2
    const int bn = blockIdx.y;        // 0..728

    // im2col k -> x-offset table
    for (int k = tid; k < KTOT; k += 256) {
        int ci = k / 9, r9 = k - ci * 9;
        int kh = r9 / 3, kw = r9 - kh * 3;
        *(uint32_t*)(smem + OFF_KOFF + k * 4) = (uint32_t)(ci * 3136 + kh * 56 + kw);
    }

    // A copy source: pre-split tiles, linear 64B per thread per chunk
    const unsigned char* aBase = g_asplit + (size_t)bm * KCH * TILE_BYTES
                               + (size_t)tid * 64;
    const uint32_t aDst = sb + (uint32_t)tid * 64;

    // B producer invariants
    const int prow = tid >> 1, khalf = tid & 1;
    const int ng = bn * 128 + prow;
    const int bimg = ng / NPIMG;
    const int prem = ng - bimg * NPIMG;
    const int oh = prem / 54, ow = prem - oh * 54;
    const __nv_bfloat162* xb = g_xpack + (size_t)bimg * XIMG + oh * 56 + ow;
    const uint32_t pswz = (uint32_t)((prow >> 1) & 3) << 4;
    const uint32_t koffs = sb + OFF_KOFF;

    // MMA invariants: warp grid 2(m) x 4(n)
    const int lane = tid & 31, wid = tid >> 5;
    const int wm = wid & 1, wn = wid >> 1;
    const uint32_t aRowOff = (uint32_t)(wm * 64 + (lane & 15)) * 64;
    const uint32_t aKext   = (uint32_t)(lane >> 4) << 4;
    const uint32_t aSwz    = (uint32_t)(((lane & 15) >> 1) & 3) << 4;
    const uint32_t bRowOff = (uint32_t)(wn * 32 + (lane & 7) + ((lane >> 4) << 3)) * 64;
    const uint32_t bKext   = (uint32_t)((lane >> 3) & 1) << 4;
    const uint32_t bSwz    = (uint32_t)(((lane & 7) >> 1) & 3) << 4;

    float acc[4][4][4];
    #pragma unroll
    for (int i = 0; i < 4; ++i)
        #pragma unroll
        for (int j = 0; j < 4; ++j)
            #pragma unroll
            for (int r = 0; r < 4; ++r) acc[i][j][r] = 0.0f;

    __syncthreads();                      // koff table ready

    // prologue: stage 0
    #pragma unroll
    for (int j = 0; j < 4; ++j)
        cpasync16(aDst + j * 16, aBase + j * 16);
    cp_commit();
    produce_b(0, sb, xb, koffs, prow, khalf, pswz);
    cp_wait0();
    __syncthreads();

    for (int ch = 0; ch < KCH; ++ch) {
        const uint32_t cur = sb + (uint32_t)(ch & 1) * STAGE_BYTES;
        const uint32_t nxt = sb + (uint32_t)((ch + 1) & 1) * STAGE_BYTES;
        if (ch + 1 < KCH) {
            const unsigned char* aSrc = aBase + (size_t)(ch + 1) * TILE_BYTES;
            const uint32_t aD = nxt + (uint32_t)tid * 64 - sb + sb; // = nxt + tid*64
            #pragma unroll
            for (int j = 0; j < 4; ++j)
                cpasync16(nxt + (uint32_t)tid * 64 - 0 + j * 16 - (uint32_t)tid * 64 + (uint32_t)tid * 64, aSrc + j * 16);
            cp_commit();
            produce_b(ch + 1, nxt, xb, koffs, prow, khalf, pswz);
            (void)aD;
        }
        mma_chunk(cur, acc, aRowOff, aKext, aSwz, bRowOff, bKext, bSwz);
        cp_wait0();
        __syncthreads();
    }

    // epilogue: acc[am][an] rows co, co+8 ; cols gn, gn+1 (float2, same image)
    const int lane4 = lane >> 2, lane2 = (lane & 3) * 2;
    #pragma unroll
    for (int an = 0; an < 4; ++an) {
        const int gn = bn * 128 + wn * 32 + an * 8 + lane2;
        const int b2 = gn / NPIMG;
        const int r2 = gn - b2 * NPIMG;
        float* op = out + (size_t)b2 * OUTIMG + r2;
        #pragma unroll
        for (int am = 0; am < 4; ++am) {
            const int co = bm * 128 + wm * 64 + am * 16 + lane4;
            *(float2*)(op + (size_t)co * NPIMG) =
                make_float2(acc[am][an][0], acc[am][an][1]);
            *(float2*)(op + (size_t)(co + 8) * NPIMG) =
                make_float2(acc[am][an][2], acc[am][an][3]);
        }
    }
}

// ---------------------------------------------------------------------------
extern "C" void kernel_launch(void* const* d_in, const int* in_sizes, int n_in,
                              void* d_out, int out_size)
{
    const float* x = (const float*)d_in[0];   // [32,256,56,56]
    const float* w = (const float*)d_in[1];   // [512,256,3,3]
    float* out = (float*)d_out;               // [32,512,54,54]

    cudaFuncSetAttribute(conv_mma_kernel,
                         cudaFuncAttributeMaxDynamicSharedMemorySize, SMEM_BYTES);

    pack_x_kernel<<<25088, 256>>>(x);
    prep_a<<<576, 256>>>(w);
    conv_mma_kernel<<<dim3(4, 729), 256, SMEM_BYTES>>>(out);
}

// round 6
// speedup vs baseline: 1.6925x; 1.2161x over previous
#include <cuda_runtime.h>
#include <cuda_fp16.h>
#include <cstdint>

// ============================================================================
// fp16 2-term split mma.sync implicit-GEMM conv, round 6.
// D = (ah + al) * bh ; A = w * 64 split into fp16 hi+lo (residual 2^-22),
// B = x as single fp16 (truncation 2^-11 -> rel_err ~3e-4 << 1e-3).
// Epilogue scales by 1/64. 2 MMAs per k16 (was 3 with bf16 split).
// A: prep_a pre-splits into exact swizzled smem layout, cp.async copy.
// B: inline gather of fp16 x (single plane), bm-fastest grid for L2 sharing.
// ============================================================================

#define KTOT   2304
#define KCH    72            // 2304 / 32
#define NPIMG  2916
#define OUTIMG (512*NPIMG)
#define XIMG   (256*3136)

#define A_TILE      16384    // [Ahi 8KB][Alo 8KB]
#define STAGE_BYTES 24576    // A 16KB + B 8KB
#define OFF_B       16384
#define OFF_KOFF    49152                  // after 2 stages
#define SMEM_BYTES  (OFF_KOFF + KTOT*4)    // 58368

// A pre-split (scaled x64) in swizzled smem-tile layout: [mt(4)][ch(72)][hi|lo]
__device__ __align__(16) unsigned char g_asplit[4ull*72*16384];   // 4.7MB
// x as fp16, single plane
__device__ __align__(16) __half g_xh[32 * 256 * 56 * 56];         // 51.4MB

// ---------------------------------------------------------------------------
__device__ __forceinline__ uint32_t smem_u32(const void* p) {
    uint32_t a;
    asm("{ .reg .u64 t; cvta.to.shared.u64 t, %1; cvt.u32.u64 %0, t; }"
        : "=r"(a) : "l"(p));
    return a;
}
__device__ __forceinline__ void sts64(uint32_t addr, uint32_t a, uint32_t b) {
    asm volatile("st.shared.v2.b32 [%0], {%1, %2};" :: "r"(addr), "r"(a), "r"(b));
}
__device__ __forceinline__ void ldsm4(uint32_t a, uint32_t& r0, uint32_t& r1,
                                      uint32_t& r2, uint32_t& r3) {
    asm volatile("ldmatrix.sync.aligned.m8n8.x4.shared.b16 {%0,%1,%2,%3}, [%4];"
                 : "=r"(r0), "=r"(r1), "=r"(r2), "=r"(r3) : "r"(a));
}
__device__ __forceinline__ void mma_f16(float* c, const uint32_t* a,
                                        uint32_t b0, uint32_t b1) {
    asm volatile(
        "mma.sync.aligned.m16n8k16.row.col.f32.f16.f16.f32 "
        "{%0,%1,%2,%3}, {%4,%5,%6,%7}, {%8,%9}, {%0,%1,%2,%3};"
        : "+f"(c[0]), "+f"(c[1]), "+f"(c[2]), "+f"(c[3])
        : "r"(a[0]), "r"(a[1]), "r"(a[2]), "r"(a[3]), "r"(b0), "r"(b1));
}
__device__ __forceinline__ void cpasync16(uint32_t dst, const void* src) {
    asm volatile("cp.async.cg.shared.global [%0], [%1], 16;"
                 :: "r"(dst), "l"(src) : "memory");
}
__device__ __forceinline__ void cp_commit() {
    asm volatile("cp.async.commit_group;" ::: "memory");
}
__device__ __forceinline__ void cp_wait0() {
    asm volatile("cp.async.wait_group 0;" ::: "memory");
}

// fp16 hi/lo split of two scaled floats, packed into u32 plane words
__device__ __forceinline__ void split2h(float a, float b, uint32_t& h, uint32_t& l) {
    __half ha = __float2half_rn(a);
    __half hb = __float2half_rn(b);
    __half la = __float2half_rn(a - __half2float(ha));
    __half lb = __float2half_rn(b - __half2float(hb));
    h = (uint32_t)*(uint16_t*)&ha | ((uint32_t)*(uint16_t*)&hb << 16);
    l = (uint32_t)*(uint16_t*)&la | ((uint32_t)*(uint16_t*)&lb << 16);
}

// ---------------------------------------------------------------------------
// prep kernels
// ---------------------------------------------------------------------------
__global__ void pack_x_kernel(const float* __restrict__ x) {
    int i = blockIdx.x * blockDim.x + threadIdx.x;   // 6422528 total
    float4 v = ((const float4*)x)[i];
    __half h0 = __float2half_rn(v.x), h1 = __float2half_rn(v.y);
    __half h2 = __float2half_rn(v.z), h3 = __float2half_rn(v.w);
    uint32_t w0 = (uint32_t)*(uint16_t*)&h0 | ((uint32_t)*(uint16_t*)&h1 << 16);
    uint32_t w1 = (uint32_t)*(uint16_t*)&h2 | ((uint32_t)*(uint16_t*)&h3 << 16);
    ((uint2*)g_xh)[i] = make_uint2(w0, w1);
}
__global__ void prep_a(const float* __restrict__ w) {
    int i = blockIdx.x * 256 + threadIdx.x;          // 147456 total
    int co = i / 288;
    int r  = i - co * 288;
    int ch = r >> 2, kq = r & 3;
    const float4* p = (const float4*)(w + (size_t)co * KTOT + ch * 32 + kq * 8);
    float4 v0 = p[0], v1 = p[1];
    uint32_t h[4], l[4];
    split2h(v0.x * 64.f, v0.y * 64.f, h[0], l[0]);
    split2h(v0.z * 64.f, v0.w * 64.f, h[1], l[1]);
    split2h(v1.x * 64.f, v1.y * 64.f, h[2], l[2]);
    split2h(v1.z * 64.f, v1.w * 64.f, h[3], l[3]);
    int m = co & 127;
    size_t base = ((size_t)(co >> 7) * KCH + ch) * A_TILE
                + m * 64 + (((uint32_t)kq * 16) ^ ((((uint32_t)m >> 1) & 3) << 4));
    *(uint4*)(g_asplit + base)        = make_uint4(h[0], h[1], h[2], h[3]);
    *(uint4*)(g_asplit + base + 8192) = make_uint4(l[0], l[1], l[2], l[3]);
}

// ---------------------------------------------------------------------------
// B producer: one 32-k chunk of fp16 im2col x into buffer bufb (single plane).
// thread -> (row n = tid>>1, khalf = tid&1); 16 LDG.16 + 4 STS.64
// ---------------------------------------------------------------------------
__device__ __forceinline__ void produce_b(
    int ch, uint32_t bufb, const __half* xb,
    uint32_t koffs, int prow, int khalf, uint32_t pswz)
{
    uint16_t bx[16];
    const uint32_t kb4 = koffs + (uint32_t)(ch * 32 + khalf * 16) * 4;
    #pragma unroll
    for (int g = 0; g < 4; ++g) {
        uint32_t k0, k1, k2, k3;
        asm volatile("ld.shared.v4.b32 {%0,%1,%2,%3}, [%4];"
                     : "=r"(k0), "=r"(k1), "=r"(k2), "=r"(k3)
                     : "r"(kb4 + g * 16));
        bx[4*g+0] = *(const uint16_t*)(xb + k0);
        bx[4*g+1] = *(const uint16_t*)(xb + k1);
        bx[4*g+2] = *(const uint16_t*)(xb + k2);
        bx[4*g+3] = *(const uint16_t*)(xb + k3);
    }
    const uint32_t sB = bufb + OFF_B + (uint32_t)prow * 64;
    const uint32_t kobase = (uint32_t)khalf * 32;
    #pragma unroll
    for (int g = 0; g < 4; ++g) {
        uint32_t w0 = (uint32_t)bx[4*g+0] | ((uint32_t)bx[4*g+1] << 16);
        uint32_t w1 = (uint32_t)bx[4*g+2] | ((uint32_t)bx[4*g+3] << 16);
        sts64(sB + ((kobase + 8u * g) ^ pswz), w0, w1);
    }
}

// ---------------------------------------------------------------------------
// MMA consumer on one 32-k chunk. buf: [Ahi 0][Alo 8K][B 16K]
// ---------------------------------------------------------------------------
__device__ __forceinline__ void mma_chunk(
    uint32_t bufb, float (&acc)[4][4][4],
    uint32_t aRowOff, uint32_t aKext, uint32_t aSwz,
    uint32_t bRowOff, uint32_t bKext, uint32_t bSwz)
{
    #pragma unroll
    for (int kb = 0; kb < 2; ++kb) {
        const uint32_t kb2 = (uint32_t)kb * 32;
        const uint32_t aK = (kb2 + aKext) ^ aSwz;
        const uint32_t bK = (kb2 + bKext) ^ bSwz;

        uint32_t bh[8];
        const uint32_t bAddr = bufb + OFF_B + bRowOff + bK;
        ldsm4(bAddr,        bh[0], bh[1], bh[2], bh[3]);
        ldsm4(bAddr + 1024, bh[4], bh[5], bh[6], bh[7]);

        uint32_t a[16];
        const uint32_t aAddr = bufb + aRowOff + aK;
        #pragma unroll
        for (int am = 0; am < 4; ++am)
            ldsm4(aAddr + am * 1024, a[4*am], a[4*am+1], a[4*am+2], a[4*am+3]);

        #pragma unroll
        for (int am = 0; am < 4; ++am)
            #pragma unroll
            for (int an = 0; an < 4; ++an)
                mma_f16(acc[am][an], a + 4*am, bh[2*an], bh[2*an+1]);

        #pragma unroll
        for (int am = 0; am < 4; ++am)
            ldsm4(aAddr + 8192 + am * 1024, a[4*am], a[4*am+1], a[4*am+2], a[4*am+3]);

        #pragma unroll
        for (int am = 0; am < 4; ++am)
            #pragma unroll
            for (int an = 0; an < 4; ++an)
                mma_f16(acc[am][an], a + 4*am, bh[2*an], bh[2*an+1]);
    }
}

// ---------------------------------------------------------------------------
__global__ void __launch_bounds__(256, 2)
conv_mma_kernel(float* __restrict__ out)
{
    extern __shared__ char smem[];
    const uint32_t sb = smem_u32(smem);
    const int tid = threadIdx.x;
    const int bm = blockIdx.x;        // 0..3, fastest -> x gathers shared in L2
    const int bn = blockIdx.y;        // 0..728

    // im2col k -> x-offset table
    for (int k = tid; k < KTOT; k += 256) {
        int ci = k / 9, r9 = k - ci * 9;
        int kh = r9 / 3, kw = r9 - kh * 3;
        *(uint32_t*)(smem + OFF_KOFF + k * 4) = (uint32_t)(ci * 3136 + kh * 56 + kw);
    }

    // A copy: pre-split tiles, 64B per thread per chunk
    const unsigned char* aBase = g_asplit + (size_t)bm * KCH * A_TILE
                               + (size_t)tid * 64;
    const uint32_t aOff = (uint32_t)tid * 64;

    // B producer invariants
    const int prow = tid >> 1, khalf = tid & 1;
    const int ng = bn * 128 + prow;
    const int bimg = ng / NPIMG;
    const int prem = ng - bimg * NPIMG;
    const int oh = prem / 54, ow = prem - oh * 54;
    const __half* xb = g_xh + (size_t)bimg * XIMG + oh * 56 + ow;
    const uint32_t pswz = (uint32_t)((prow >> 1) & 3) << 4;
    const uint32_t koffs = sb + OFF_KOFF;

    // MMA invariants: warp grid 2(m) x 4(n)
    const int lane = tid & 31, wid = tid >> 5;
    const int wm = wid & 1, wn = wid >> 1;
    const uint32_t aRowOff = (uint32_t)(wm * 64 + (lane & 15)) * 64;
    const uint32_t aKext   = (uint32_t)(lane >> 4) << 4;
    const uint32_t aSwz    = (uint32_t)(((lane & 15) >> 1) & 3) << 4;
    const uint32_t bRowOff = (uint32_t)(wn * 32 + (lane & 7) + ((lane >> 4) << 3)) * 64;
    const uint32_t bKext   = (uint32_t)((lane >> 3) & 1) << 4;
    const uint32_t bSwz    = (uint32_t)(((lane & 7) >> 1) & 3) << 4;

    float acc[4][4][4];
    #pragma unroll
    for (int i = 0; i < 4; ++i)
        #pragma unroll
        for (int j = 0; j < 4; ++j)
            #pragma unroll
            for (int r = 0; r < 4; ++r) acc[i][j][r] = 0.0f;

    __syncthreads();                      // koff table ready

    // prologue: stage 0
    #pragma unroll
    for (int j = 0; j < 4; ++j)
        cpasync16(sb + aOff + j * 16, aBase + j * 16);
    cp_commit();
    produce_b(0, sb, xb, koffs, prow, khalf, pswz);
    cp_wait0();
    __syncthreads();

    for (int ch = 0; ch < KCH; ++ch) {
        const uint32_t cur = sb + (uint32_t)(ch & 1) * STAGE_BYTES;
        const uint32_t nxt = sb + (uint32_t)((ch + 1) & 1) * STAGE_BYTES;
        if (ch + 1 < KCH) {
            const unsigned char* aSrc = aBase + (size_t)(ch + 1) * A_TILE;
            #pragma unroll
            for (int j = 0; j < 4; ++j)
                cpasync16(nxt + aOff + j * 16, aSrc + j * 16);
            cp_commit();
            produce_b(ch + 1, nxt, xb, koffs, prow, khalf, pswz);
        }
        mma_chunk(cur, acc, aRowOff, aKext, aSwz, bRowOff, bKext, bSwz);
        cp_wait0();
        __syncthreads();
    }

    // epilogue: scale by 1/64; acc[am][an] rows co, co+8 ; cols gn, gn+1
    const float s = 0.015625f;
    const int lane4 = lane >> 2, lane2 = (lane & 3) * 2;
    #pragma unroll
    for (int an = 0; an < 4; ++an) {
        const int gn = bn * 128 + wn * 32 + an * 8 + lane2;
        const int b2 = gn / NPIMG;
        const int r2 = gn - b2 * NPIMG;
        float* op = out + (size_t)b2 * OUTIMG + r2;
        #pragma unroll
        for (int am = 0; am < 4; ++am) {
            const int co = bm * 128 + wm * 64 + am * 16 + lane4;
            *(float2*)(op + (size_t)co * NPIMG) =
                make_float2(acc[am][an][0] * s, acc[am][an][1] * s);
            *(float2*)(op + (size_t)(co + 8) * NPIMG) =
                make_float2(acc[am][an][2] * s, acc[am][an][3] * s);
        }
    }
}

// ---------------------------------------------------------------------------
extern "C" void kernel_launch(void* const* d_in, const int* in_sizes, int n_in,
                              void* d_out, int out_size)
{
    const float* x = (const float*)d_in[0];   // [32,256,56,56]
    const float* w = (const float*)d_in[1];   // [512,256,3,3]
    float* out = (float*)d_out;               // [32,512,54,54]

    cudaFuncSetAttribute(conv_mma_kernel,
                         cudaFuncAttributeMaxDynamicSharedMemorySize, SMEM_BYTES);

    pack_x_kernel<<<25088, 256>>>(x);
    prep_a<<<576, 256>>>(w);
    conv_mma_kernel<<<dim3(4, 729), 256, SMEM_BYTES>>>(out);
}

// round 7
// speedup vs baseline: 1.7239x; 1.0186x over previous
#include <cuda_runtime.h>
#include <cuda_fp16.h>
#include <cstdint>

// ============================================================================
// Single-term fp16 mma.sync implicit-GEMM conv, round 7.
// D = ah * bh ; A = w*64 -> fp16 (epilogue * 1/64), B = x -> fp16.
// Error budget: A-trunc + B-trunc, measured-B-only was 2.08e-4 -> ~2.9e-4.
// 1 MMA per k16 (was 2). A: prep_a pre-split/swizzled, cp.async copy.
// B: inline fp16 gather, bm-fastest grid for L2 sharing of x.
// ============================================================================

#define KTOT   2304
#define KCH    72            // 2304 / 32
#define NPIMG  2916
#define OUTIMG (512*NPIMG)
#define XIMG   (256*3136)

#define A_TILE      8192     // single fp16 plane, 128 rows x 64B
#define STAGE_BYTES 16384    // A 8KB + B 8KB
#define OFF_B       8192
#define OFF_KOFF    32768                  // after 2 stages
#define SMEM_BYTES  (OFF_KOFF + KTOT*4)    // 41984

// A (scaled x64, fp16) in exact swizzled smem-tile layout: [mt(4)][ch(72)][8KB]
__device__ __align__(16) unsigned char g_asplit[4ull*72*8192];    // 2.4MB
// x as fp16
__device__ __align__(16) __half g_xh[32 * 256 * 56 * 56];         // 51.4MB

// ---------------------------------------------------------------------------
__device__ __forceinline__ uint32_t smem_u32(const void* p) {
    uint32_t a;
    asm("{ .reg .u64 t; cvta.to.shared.u64 t, %1; cvt.u32.u64 %0, t; }"
        : "=r"(a) : "l"(p));
    return a;
}
__device__ __forceinline__ void sts64(uint32_t addr, uint32_t a, uint32_t b) {
    asm volatile("st.shared.v2.b32 [%0], {%1, %2};" :: "r"(addr), "r"(a), "r"(b));
}
__device__ __forceinline__ void ldsm4(uint32_t a, uint32_t& r0, uint32_t& r1,
                                      uint32_t& r2, uint32_t& r3) {
    asm volatile("ldmatrix.sync.aligned.m8n8.x4.shared.b16 {%0,%1,%2,%3}, [%4];"
                 : "=r"(r0), "=r"(r1), "=r"(r2), "=r"(r3) : "r"(a));
}
__device__ __forceinline__ void mma_f16(float* c, const uint32_t* a,
                                        uint32_t b0, uint32_t b1) {
    asm volatile(
        "mma.sync.aligned.m16n8k16.row.col.f32.f16.f16.f32 "
        "{%0,%1,%2,%3}, {%4,%5,%6,%7}, {%8,%9}, {%0,%1,%2,%3};"
        : "+f"(c[0]), "+f"(c[1]), "+f"(c[2]), "+f"(c[3])
        : "r"(a[0]), "r"(a[1]), "r"(a[2]), "r"(a[3]), "r"(b0), "r"(b1));
}
__device__ __forceinline__ void cpasync16(uint32_t dst, const void* src) {
    asm volatile("cp.async.cg.shared.global [%0], [%1], 16;"
                 :: "r"(dst), "l"(src) : "memory");
}
__device__ __forceinline__ void cp_commit() {
    asm volatile("cp.async.commit_group;" ::: "memory");
}
__device__ __forceinline__ void cp_wait0() {
    asm volatile("cp.async.wait_group 0;" ::: "memory");
}

// ---------------------------------------------------------------------------
// prep kernels
// ---------------------------------------------------------------------------
__global__ void pack_x_kernel(const float* __restrict__ x) {
    int i = blockIdx.x * blockDim.x + threadIdx.x;   // 6422528 total
    float4 v = ((const float4*)x)[i];
    __half h0 = __float2half_rn(v.x), h1 = __float2half_rn(v.y);
    __half h2 = __float2half_rn(v.z), h3 = __float2half_rn(v.w);
    uint32_t w0 = (uint32_t)*(uint16_t*)&h0 | ((uint32_t)*(uint16_t*)&h1 << 16);
    uint32_t w1 = (uint32_t)*(uint16_t*)&h2 | ((uint32_t)*(uint16_t*)&h3 << 16);
    ((uint2*)g_xh)[i] = make_uint2(w0, w1);
}
__global__ void prep_a(const float* __restrict__ w) {
    int i = blockIdx.x * 256 + threadIdx.x;          // 147456 total
    int co = i / 288;
    int r  = i - co * 288;
    int ch = r >> 2, kq = r & 3;
    const float4* p = (const float4*)(w + (size_t)co * KTOT + ch * 32 + kq * 8);
    float4 v0 = p[0], v1 = p[1];
    __half a0 = __float2half_rn(v0.x * 64.f), a1 = __float2half_rn(v0.y * 64.f);
    __half a2 = __float2half_rn(v0.z * 64.f), a3 = __float2half_rn(v0.w * 64.f);
    __half a4 = __float2half_rn(v1.x * 64.f), a5 = __float2half_rn(v1.y * 64.f);
    __half a6 = __float2half_rn(v1.z * 64.f), a7 = __float2half_rn(v1.w * 64.f);
    uint32_t h0 = (uint32_t)*(uint16_t*)&a0 | ((uint32_t)*(uint16_t*)&a1 << 16);
    uint32_t h1 = (uint32_t)*(uint16_t*)&a2 | ((uint32_t)*(uint16_t*)&a3 << 16);
    uint32_t h2 = (uint32_t)*(uint16_t*)&a4 | ((uint32_t)*(uint16_t*)&a5 << 16);
    uint32_t h3 = (uint32_t)*(uint16_t*)&a6 | ((uint32_t)*(uint16_t*)&a7 << 16);
    int m = co & 127;
    size_t base = ((size_t)(co >> 7) * KCH + ch) * A_TILE
                + m * 64 + (((uint32_t)kq * 16) ^ ((((uint32_t)m >> 1) & 3) << 4));
    *(uint4*)(g_asplit + base) = make_uint4(h0, h1, h2, h3);
}

// ---------------------------------------------------------------------------
// B producer: one 32-k chunk of fp16 im2col x into buffer bufb.
// thread -> (row n = tid>>1, khalf = tid&1); 16 LDG.16 + 4 STS.64
// ---------------------------------------------------------------------------
__device__ __forceinline__ void produce_b(
    int ch, uint32_t bufb, const __half* xb,
    uint32_t koffs, int prow, int khalf, uint32_t pswz)
{
    uint16_t bx[16];
    const uint32_t kb4 = koffs + (uint32_t)(ch * 32 + khalf * 16) * 4;
    #pragma unroll
    for (int g = 0; g < 4; ++g) {
        uint32_t k0, k1, k2, k3;
        asm volatile("ld.shared.v4.b32 {%0,%1,%2,%3}, [%4];"
                     : "=r"(k0), "=r"(k1), "=r"(k2), "=r"(k3)
                     : "r"(kb4 + g * 16));
        bx[4*g+0] = *(const uint16_t*)(xb + k0);
        bx[4*g+1] = *(const uint16_t*)(xb + k1);
        bx[4*g+2] = *(const uint16_t*)(xb + k2);
        bx[4*g+3] = *(const uint16_t*)(xb + k3);
    }
    const uint32_t sB = bufb + OFF_B + (uint32_t)prow * 64;
    const uint32_t kobase = (uint32_t)khalf * 32;
    #pragma unroll
    for (int g = 0; g < 4; ++g) {
        uint32_t w0 = (uint32_t)bx[4*g+0] | ((uint32_t)bx[4*g+1] << 16);
        uint32_t w1 = (uint32_t)bx[4*g+2] | ((uint32_t)bx[4*g+3] << 16);
        sts64(sB + ((kobase + 8u * g) ^ pswz), w0, w1);
    }
}

// ---------------------------------------------------------------------------
// MMA consumer on one 32-k chunk. buf: [A 0][B 8K]
// ---------------------------------------------------------------------------
__device__ __forceinline__ void mma_chunk(
    uint32_t bufb, float (&acc)[4][4][4],
    uint32_t aRowOff, uint32_t aKext, uint32_t aSwz,
    uint32_t bRowOff, uint32_t bKext, uint32_t bSwz)
{
    #pragma unroll
    for (int kb = 0; kb < 2; ++kb) {
        const uint32_t kb2 = (uint32_t)kb * 32;
        const uint32_t aK = (kb2 + aKext) ^ aSwz;
        const uint32_t bK = (kb2 + bKext) ^ bSwz;

        uint32_t bh[8];
        const uint32_t bAddr = bufb + OFF_B + bRowOff + bK;
        ldsm4(bAddr,        bh[0], bh[1], bh[2], bh[3]);
        ldsm4(bAddr + 1024, bh[4], bh[5], bh[6], bh[7]);

        uint32_t a[16];
        const uint32_t aAddr = bufb + aRowOff + aK;
        #pragma unroll
        for (int am = 0; am < 4; ++am)
            ldsm4(aAddr + am * 1024, a[4*am], a[4*am+1], a[4*am+2], a[4*am+3]);

        #pragma unroll
        for (int am = 0; am < 4; ++am)
            #pragma unroll
            for (int an = 0; an < 4; ++an)
                mma_f16(acc[am][an], a + 4*am, bh[2*an], bh[2*an+1]);
    }
}

// ---------------------------------------------------------------------------
__global__ void __launch_bounds__(256, 2)
conv_mma_kernel(float* __restrict__ out)
{
    extern __shared__ char smem[];
    const uint32_t sb = smem_u32(smem);
    const int tid = threadIdx.x;
    const int bm = blockIdx.x;        // 0..3, fastest -> x gathers shared in L2
    const int bn = blockIdx.y;        // 0..728

    // im2col k -> x-offset table
    for (int k = tid; k < KTOT; k += 256) {
        int ci = k / 9, r9 = k - ci * 9;
        int kh = r9 / 3, kw = r9 - kh * 3;
        *(uint32_t*)(smem + OFF_KOFF + k * 4) = (uint32_t)(ci * 3136 + kh * 56 + kw);
    }

    // A copy: 32B per thread per chunk
    const unsigned char* aBase = g_asplit + (size_t)bm * KCH * A_TILE
                               + (size_t)tid * 32;
    const uint32_t aOff = (uint32_t)tid * 32;

    // B producer invariants
    const int prow = tid >> 1, khalf = tid & 1;
    const int ng = bn * 128 + prow;
    const int bimg = ng / NPIMG;
    const int prem = ng - bimg * NPIMG;
    const int oh = prem / 54, ow = prem - oh * 54;
    const __half* xb = g_xh + (size_t)bimg * XIMG + oh * 56 + ow;
    const uint32_t pswz = (uint32_t)((prow >> 1) & 3) << 4;
    const uint32_t koffs = sb + OFF_KOFF;

    // MMA invariants: warp grid 2(m) x 4(n)
    const int lane = tid & 31, wid = tid >> 5;
    const int wm = wid & 1, wn = wid >> 1;
    const uint32_t aRowOff = (uint32_t)(wm * 64 + (lane & 15)) * 64;
    const uint32_t aKext   = (uint32_t)(lane >> 4) << 4;
    const uint32_t aSwz    = (uint32_t)(((lane & 15) >> 1) & 3) << 4;
    const uint32_t bRowOff = (uint32_t)(wn * 32 + (lane & 7) + ((lane >> 4) << 3)) * 64;
    const uint32_t bKext   = (uint32_t)((lane >> 3) & 1) << 4;
    const uint32_t bSwz    = (uint32_t)(((lane & 7) >> 1) & 3) << 4;

    float acc[4][4][4];
    #pragma unroll
    for (int i = 0; i < 4; ++i)
        #pragma unroll
        for (int j = 0; j < 4; ++j)
            #pragma unroll
            for (int r = 0; r < 4; ++r) acc[i][j][r] = 0.0f;

    __syncthreads();                      // koff table ready

    // prologue: stage 0
    cpasync16(sb + aOff,      aBase);
    cpasync16(sb + aOff + 16, aBase + 16);
    cp_commit();
    produce_b(0, sb, xb, koffs, prow, khalf, pswz);
    cp_wait0();
    __syncthreads();

    for (int ch = 0; ch < KCH; ++ch) {
        const uint32_t cur = sb + (uint32_t)(ch & 1) * STAGE_BYTES;
        const uint32_t nxt = sb + (uint32_t)((ch + 1) & 1) * STAGE_BYTES;
        if (ch + 1 < KCH) {
            const unsigned char* aSrc = aBase + (size_t)(ch + 1) * A_TILE;
            cpasync16(nxt + aOff,      aSrc);
            cpasync16(nxt + aOff + 16, aSrc + 16);
            cp_commit();
            produce_b(ch + 1, nxt, xb, koffs, prow, khalf, pswz);
        }
        mma_chunk(cur, acc, aRowOff, aKext, aSwz, bRowOff, bKext, bSwz);
        cp_wait0();
        __syncthreads();
    }

    // epilogue: scale by 1/64; acc[am][an] rows co, co+8 ; cols gn, gn+1
    const float s = 0.015625f;
    const int lane4 = lane >> 2, lane2 = (lane & 3) * 2;
    #pragma unroll
    for (int an = 0; an < 4; ++an) {
        const int gn = bn * 128 + wn * 32 + an * 8 + lane2;
        const int b2 = gn / NPIMG;
        const int r2 = gn - b2 * NPIMG;
        float* op = out + (size_t)b2 * OUTIMG + r2;
        #pragma unroll
        for (int am = 0; am < 4; ++am) {
            const int co = bm * 128 + wm * 64 + am * 16 + lane4;
            *(float2*)(op + (size_t)co * NPIMG) =
                make_float2(acc[am][an][0] * s, acc[am][an][1] * s);
            *(float2*)(op + (size_t)(co + 8) * NPIMG) =
                make_float2(acc[am][an][2] * s, acc[am][an][3] * s);
        }
    }
}

// ---------------------------------------------------------------------------
extern "C" void kernel_launch(void* const* d_in, const int* in_sizes, int n_in,
                              void* d_out, int out_size)
{
    const float* x = (const float*)d_in[0];   // [32,256,56,56]
    const float* w = (const float*)d_in[1];   // [512,256,3,3]
    float* out = (float*)d_out;               // [32,512,54,54]

    cudaFuncSetAttribute(conv_mma_kernel,
                         cudaFuncAttributeMaxDynamicSharedMemorySize, SMEM_BYTES);

    pack_x_kernel<<<25088, 256>>>(x);
    prep_a<<<576, 256>>>(w);
    conv_mma_kernel<<<dim3(4, 729), 256, SMEM_BYTES>>>(out);
}

// round 8
// speedup vs baseline: 2.8943x; 1.6789x over previous
#include <cuda_runtime.h>
#include <cuda_fp16.h>
#include <cstdint>

// ============================================================================
// Single-term fp16 mma.sync implicit-GEMM conv, round 8.
// Same math/layout as round 7 (D = ah*bh, A=w*64 fp16, B=x fp16, eps ~2.9e-4).
// Pipeline reordered: B LDGs (ch+1) issue BEFORE mma_chunk(ch), STS after --
// MMA latency hides the gather round-trip instead of serializing with it.
// ============================================================================

#define KTOT   2304
#define KCH    72            // 2304 / 32
#define NPIMG  2916
#define OUTIMG (512*NPIMG)
#define XIMG   (256*3136)

#define A_TILE      8192     // single fp16 plane, 128 rows x 64B
#define STAGE_BYTES 16384    // A 8KB + B 8KB
#define OFF_B       8192
#define OFF_KOFF    32768                  // after 2 stages
#define SMEM_BYTES  (OFF_KOFF + KTOT*4)    // 41984

// A (scaled x64, fp16) in exact swizzled smem-tile layout: [mt(4)][ch(72)][8KB]
__device__ __align__(16) unsigned char g_asplit[4ull*72*8192];    // 2.4MB
// x as fp16
__device__ __align__(16) __half g_xh[32 * 256 * 56 * 56];         // 51.4MB

// ---------------------------------------------------------------------------
__device__ __forceinline__ uint32_t smem_u32(const void* p) {
    uint32_t a;
    asm("{ .reg .u64 t; cvta.to.shared.u64 t, %1; cvt.u32.u64 %0, t; }"
        : "=r"(a) : "l"(p));
    return a;
}
__device__ __forceinline__ void sts64(uint32_t addr, uint32_t a, uint32_t b) {
    asm volatile("st.shared.v2.b32 [%0], {%1, %2};" :: "r"(addr), "r"(a), "r"(b));
}
__device__ __forceinline__ void ldsm4(uint32_t a, uint32_t& r0, uint32_t& r1,
                                      uint32_t& r2, uint32_t& r3) {
    asm volatile("ldmatrix.sync.aligned.m8n8.x4.shared.b16 {%0,%1,%2,%3}, [%4];"
                 : "=r"(r0), "=r"(r1), "=r"(r2), "=r"(r3) : "r"(a));
}
__device__ __forceinline__ void mma_f16(float* c, const uint32_t* a,
                                        uint32_t b0, uint32_t b1) {
    asm volatile(
        "mma.sync.aligned.m16n8k16.row.col.f32.f16.f16.f32 "
        "{%0,%1,%2,%3}, {%4,%5,%6,%7}, {%8,%9}, {%0,%1,%2,%3};"
        : "+f"(c[0]), "+f"(c[1]), "+f"(c[2]), "+f"(c[3])
        : "r"(a[0]), "r"(a[1]), "r"(a[2]), "r"(a[3]), "r"(b0), "r"(b1));
}
__device__ __forceinline__ void cpasync16(uint32_t dst, const void* src) {
    asm volatile("cp.async.cg.shared.global [%0], [%1], 16;"
                 :: "r"(dst), "l"(src) : "memory");
}
__device__ __forceinline__ void cp_commit() {
    asm volatile("cp.async.commit_group;" ::: "memory");
}
__device__ __forceinline__ void cp_wait0() {
    asm volatile("cp.async.wait_group 0;" ::: "memory");
}

// ---------------------------------------------------------------------------
// prep kernels (unchanged from round 7)
// ---------------------------------------------------------------------------
__global__ void pack_x_kernel(const float* __restrict__ x) {
    int i = blockIdx.x * blockDim.x + threadIdx.x;   // 6422528 total
    float4 v = ((const float4*)x)[i];
    __half h0 = __float2half_rn(v.x), h1 = __float2half_rn(v.y);
    __half h2 = __float2half_rn(v.z), h3 = __float2half_rn(v.w);
    uint32_t w0 = (uint32_t)*(uint16_t*)&h0 | ((uint32_t)*(uint16_t*)&h1 << 16);
    uint32_t w1 = (uint32_t)*(uint16_t*)&h2 | ((uint32_t)*(uint16_t*)&h3 << 16);
    ((uint2*)g_xh)[i] = make_uint2(w0, w1);
}
__global__ void prep_a(const float* __restrict__ w) {
    int i = blockIdx.x * 256 + threadIdx.x;          // 147456 total
    int co = i / 288;
    int r  = i - co * 288;
    int ch = r >> 2, kq = r & 3;
    const float4* p = (const float4*)(w + (size_t)co * KTOT + ch * 32 + kq * 8);
    float4 v0 = p[0], v1 = p[1];
    __half a0 = __float2half_rn(v0.x * 64.f), a1 = __float2half_rn(v0.y * 64.f);
    __half a2 = __float2half_rn(v0.z * 64.f), a3 = __float2half_rn(v0.w * 64.f);
    __half a4 = __float2half_rn(v1.x * 64.f), a5 = __float2half_rn(v1.y * 64.f);
    __half a6 = __float2half_rn(v1.z * 64.f), a7 = __float2half_rn(v1.w * 64.f);
    uint32_t h0 = (uint32_t)*(uint16_t*)&a0 | ((uint32_t)*(uint16_t*)&a1 << 16);
    uint32_t h1 = (uint32_t)*(uint16_t*)&a2 | ((uint32_t)*(uint16_t*)&a3 << 16);
    uint32_t h2 = (uint32_t)*(uint16_t*)&a4 | ((uint32_t)*(uint16_t*)&a5 << 16);
    uint32_t h3 = (uint32_t)*(uint16_t*)&a6 | ((uint32_t)*(uint16_t*)&a7 << 16);
    int m = co & 127;
    size_t base = ((size_t)(co >> 7) * KCH + ch) * A_TILE
                + m * 64 + (((uint32_t)kq * 16) ^ ((((uint32_t)m >> 1) & 3) << 4));
    *(uint4*)(g_asplit + base) = make_uint4(h0, h1, h2, h3);
}

// ---------------------------------------------------------------------------
// B producer split: load phase (LDG -> regs) / store phase (regs -> smem)
// ---------------------------------------------------------------------------
__device__ __forceinline__ void load_b(
    int ch, const __half* xb, uint32_t koffs, int khalf, uint16_t (&bx)[16])
{
    const uint32_t kb4 = koffs + (uint32_t)(ch * 32 + khalf * 16) * 4;
    #pragma unroll
    for (int g = 0; g < 4; ++g) {
        uint32_t k0, k1, k2, k3;
        asm volatile("ld.shared.v4.b32 {%0,%1,%2,%3}, [%4];"
                     : "=r"(k0), "=r"(k1), "=r"(k2), "=r"(k3)
                     : "r"(kb4 + g * 16));
        bx[4*g+0] = *(const uint16_t*)(xb + k0);
        bx[4*g+1] = *(const uint16_t*)(xb + k1);
        bx[4*g+2] = *(const uint16_t*)(xb + k2);
        bx[4*g+3] = *(const uint16_t*)(xb + k3);
    }
}
__device__ __forceinline__ void store_b(
    uint32_t bufb, const uint16_t (&bx)[16], int prow, int khalf, uint32_t pswz)
{
    const uint32_t sB = bufb + OFF_B + (uint32_t)prow * 64;
    const uint32_t kobase = (uint32_t)khalf * 32;
    #pragma unroll
    for (int g = 0; g < 4; ++g) {
        uint32_t w0 = (uint32_t)bx[4*g+0] | ((uint32_t)bx[4*g+1] << 16);
        uint32_t w1 = (uint32_t)bx[4*g+2] | ((uint32_t)bx[4*g+3] << 16);
        sts64(sB + ((kobase + 8u * g) ^ pswz), w0, w1);
    }
}

// ---------------------------------------------------------------------------
// MMA consumer on one 32-k chunk. buf: [A 0][B 8K]
// ---------------------------------------------------------------------------
__device__ __forceinline__ void mma_chunk(
    uint32_t bufb, float (&acc)[4][4][4],
    uint32_t aRowOff, uint32_t aKext, uint32_t aSwz,
    uint32_t bRowOff, uint32_t bKext, uint32_t bSwz)
{
    #pragma unroll
    for (int kb = 0; kb < 2; ++kb) {
        const uint32_t kb2 = (uint32_t)kb * 32;
        const uint32_t aK = (kb2 + aKext) ^ aSwz;
        const uint32_t bK = (kb2 + bKext) ^ bSwz;

        uint32_t bh[8];
        const uint32_t bAddr = bufb + OFF_B + bRowOff + bK;
        ldsm4(bAddr,        bh[0], bh[1], bh[2], bh[3]);
        ldsm4(bAddr + 1024, bh[4], bh[5], bh[6], bh[7]);

        uint32_t a[16];
        const uint32_t aAddr = bufb + aRowOff + aK;
        #pragma unroll
        for (int am = 0; am < 4; ++am)
            ldsm4(aAddr + am * 1024, a[4*am], a[4*am+1], a[4*am+2], a[4*am+3]);

        #pragma unroll
        for (int am = 0; am < 4; ++am)
            #pragma unroll
            for (int an = 0; an < 4; ++an)
                mma_f16(acc[am][an], a + 4*am, bh[2*an], bh[2*an+1]);
    }
}

// ---------------------------------------------------------------------------
__global__ void __launch_bounds__(256, 2)
conv_mma_kernel(float* __restrict__ out)
{
    extern __shared__ char smem[];
    const uint32_t sb = smem_u32(smem);
    const int tid = threadIdx.x;
    const int bm = blockIdx.x;        // 0..3, fastest -> x gathers shared in L2
    const int bn = blockIdx.y;        // 0..728

    // im2col k -> x-offset table
    for (int k = tid; k < KTOT; k += 256) {
        int ci = k / 9, r9 = k - ci * 9;
        int kh = r9 / 3, kw = r9 - kh * 3;
        *(uint32_t*)(smem + OFF_KOFF + k * 4) = (uint32_t)(ci * 3136 + kh * 56 + kw);
    }

    // A copy: 32B per thread per chunk
    const unsigned char* aBase = g_asplit + (size_t)bm * KCH * A_TILE
                               + (size_t)tid * 32;
    const uint32_t aOff = (uint32_t)tid * 32;

    // B producer invariants
    const int prow = tid >> 1, khalf = tid & 1;
    const int ng = bn * 128 + prow;
    const int bimg = ng / NPIMG;
    const int prem = ng - bimg * NPIMG;
    const int oh = prem / 54, ow = prem - oh * 54;
    const __half* xb = g_xh + (size_t)bimg * XIMG + oh * 56 + ow;
    const uint32_t pswz = (uint32_t)((prow >> 1) & 3) << 4;
    const uint32_t koffs = sb + OFF_KOFF;

    // MMA invariants: warp grid 2(m) x 4(n)
    const int lane = tid & 31, wid = tid >> 5;
    const int wm = wid & 1, wn = wid >> 1;
    const uint32_t aRowOff = (uint32_t)(wm * 64 + (lane & 15)) * 64;
    const uint32_t aKext   = (uint32_t)(lane >> 4) << 4;
    const uint32_t aSwz    = (uint32_t)(((lane & 15) >> 1) & 3) << 4;
    const uint32_t bRowOff = (uint32_t)(wn * 32 + (lane & 7) + ((lane >> 4) << 3)) * 64;
    const uint32_t bKext   = (uint32_t)((lane >> 3) & 1) << 4;
    const uint32_t bSwz    = (uint32_t)(((lane & 7) >> 1) & 3) << 4;

    float acc[4][4][4];
    #pragma unroll
    for (int i = 0; i < 4; ++i)
        #pragma unroll
        for (int j = 0; j < 4; ++j)
            #pragma unroll
            for (int r = 0; r < 4; ++r) acc[i][j][r] = 0.0f;

    __syncthreads();                      // koff table ready

    // prologue: stage 0
    cpasync16(sb + aOff,      aBase);
    cpasync16(sb + aOff + 16, aBase + 16);
    cp_commit();
    {
        uint16_t bx0[16];
        load_b(0, xb, koffs, khalf, bx0);
        store_b(sb, bx0, prow, khalf, pswz);
    }
    cp_wait0();
    __syncthreads();

    for (int ch = 0; ch < KCH; ++ch) {
        const uint32_t cur = sb + (uint32_t)(ch & 1) * STAGE_BYTES;
        const uint32_t nxt = sb + (uint32_t)((ch + 1) & 1) * STAGE_BYTES;
        const bool pre = (ch + 1 < KCH);

        uint16_t bx[16];
        if (pre) {
            load_b(ch + 1, xb, koffs, khalf, bx);      // LDGs issue, no wait
            const unsigned char* aSrc = aBase + (size_t)(ch + 1) * A_TILE;
            cpasync16(nxt + aOff,      aSrc);
            cpasync16(nxt + aOff + 16, aSrc + 16);
            cp_commit();
        }

        mma_chunk(cur, acc, aRowOff, aKext, aSwz, bRowOff, bKext, bSwz);

        if (pre)
            store_b(nxt, bx, prow, khalf, pswz);       // LDGs landed during MMA
        cp_wait0();
        __syncthreads();
    }

    // epilogue: scale by 1/64; acc[am][an] rows co, co+8 ; cols gn, gn+1
    const float s = 0.015625f;
    const int lane4 = lane >> 2, lane2 = (lane & 3) * 2;
    #pragma unroll
    for (int an = 0; an < 4; ++an) {
        const int gn = bn * 128 + wn * 32 + an * 8 + lane2;
        const int b2 = gn / NPIMG;
        const int r2 = gn - b2 * NPIMG;
        float* op = out + (size_t)b2 * OUTIMG + r2;
        #pragma unroll
        for (int am = 0; am < 4; ++am) {
            const int co = bm * 128 + wm * 64 + am * 16 + lane4;
            *(float2*)(op + (size_t)co * NPIMG) =
                make_float2(acc[am][an][0] * s, acc[am][an][1] * s);
            *(float2*)(op + (size_t)(co + 8) * NPIMG) =
                make_float2(acc[am][an][2] * s, acc[am][an][3] * s);
        }
    }
}

// ---------------------------------------------------------------------------
extern "C" void kernel_launch(void* const* d_in, const int* in_sizes, int n_in,
                              void* d_out, int out_size)
{
    const float* x = (const float*)d_in[0];   // [32,256,56,56]
    const float* w = (const float*)d_in[1];   // [512,256,3,3]
    float* out = (float*)d_out;               // [32,512,54,54]

    cudaFuncSetAttribute(conv_mma_kernel,
                         cudaFuncAttributeMaxDynamicSharedMemorySize, SMEM_BYTES);

    pack_x_kernel<<<25088, 256>>>(x);
    prep_a<<<576, 256>>>(w);
    conv_mma_kernel<<<dim3(4, 729), 256, SMEM_BYTES>>>(out);
}